// round 4
// baseline (speedup 1.0000x reference)
#include <cuda_runtime.h>
#include <cuda_bf16.h>
#include <cstdint>

// Problem dims (fixed by reference)
#define B_   2
#define S_   2048
#define D_   1024
#define E_   1024
#define H_   16
#define HD_  64
#define MTOT (B_*S_)        // 4096
#define NQKV (3*E_)         // 3072
#define BHN  (B_*H_)        // 32

// ---- static device scratch (no allocations allowed) ----
__device__ __align__(256) float g_q[(size_t)BHN * S_ * HD_];       // [B,H,S,HD], tf32-rounded
__device__ __align__(256) float g_k[(size_t)BHN * S_ * HD_];
__device__ __align__(256) float g_v[(size_t)BHN * S_ * HD_];
__device__ __align__(256) float g_vals[(size_t)MTOT * E_];         // [B,S,E]
__device__ __align__(256) float g_out_scratch[(size_t)MTOT * D_];
__device__ __align__(256) float g_attn_scratch[(size_t)BHN * S_ * S_];

__device__ __forceinline__ uint32_t f2tf32(float x) {
    uint32_t u;
    asm("cvt.rna.tf32.f32 %0, %1;" : "=r"(u) : "f"(x));
    return u;
}

__device__ __forceinline__ void mma_tf32(float c[4], const uint32_t a[4], const uint32_t b[2]) {
    asm volatile(
        "mma.sync.aligned.m16n8k8.row.col.f32.tf32.tf32.f32 "
        "{%0,%1,%2,%3}, {%4,%5,%6,%7}, {%8,%9}, {%0,%1,%2,%3};\n"
        : "+f"(c[0]), "+f"(c[1]), "+f"(c[2]), "+f"(c[3])
        : "r"(a[0]), "r"(a[1]), "r"(a[2]), "r"(a[3]), "r"(b[0]), "r"(b[1]));
}

// ldmatrix x4: loads four 8x8 b16 tiles == four 8x4 tf32 tiles.
// Thread t supplies the row address for tile (t/8), row (t%8).
__device__ __forceinline__ void ldsm4(uint32_t& r0, uint32_t& r1, uint32_t& r2, uint32_t& r3,
                                      const uint32_t* p) {
    uint32_t a = (uint32_t)__cvta_generic_to_shared(p);
    asm volatile("ldmatrix.sync.aligned.m8n8.x4.shared.b16 {%0,%1,%2,%3}, [%4];"
                 : "=r"(r0), "=r"(r1), "=r"(r2), "=r"(r3) : "r"(a));
}

__device__ __forceinline__ void cpa16(void* s, const void* g) {
    uint32_t sa = (uint32_t)__cvta_generic_to_shared(s);
    asm volatile("cp.async.cg.shared.global [%0], [%1], 16;" :: "r"(sa), "l"(g));
}
#define CP_COMMIT asm volatile("cp.async.commit_group;")
#define CP_WAIT0  asm volatile("cp.async.wait_group 0;")

// ============================================================================
// Dense GEMMs (QKV projection / output projection), tf32 tensor cores + LDSM.
// MODE 0: qkv — A=x[4096,1024], B=w_qkv[3072,1024]; +bias, scatter q/k/v (tf32-rounded)
// MODE 3: proj — A=g_vals[4096,1024], B=w_out[1024,1024]; +bias -> out
// ============================================================================
template<int MODE>
__global__ __launch_bounds__(256)
void mma_gemm(const float* __restrict__ p0, const float* __restrict__ p1,
              const float* __restrict__ bias, float* __restrict__ pC) {
    constexpr int BM = 128, BN = 128, BK = 16;
    constexpr int KDIM = 1024;
    constexpr int KT = KDIM / BK;
    constexpr int SAS = BK + 4;   // stride 20 words: LDSM row-seg banks 5r mod 8 -> conflict-free

    __shared__ uint32_t As[2][BM * SAS];
    __shared__ uint32_t Bs[2][BN * SAS];

    const int tid = threadIdx.x;
    const int wid = tid >> 5, lane = tid & 31;
    const int g = lane >> 2, tg = lane & 3;
    const int warpM = wid / 4, warpN = wid % 4;   // 2x4 warp grid, warp tile 64x32
    const int bm = blockIdx.y * BM;
    const int bn = blockIdx.x * BN;

    // LDSM per-thread source coordinates
    const int arow = (lane & 7) + ((lane >> 3) & 1) * 8;   // A: tiles 0/2 rows+0, 1/3 rows+8
    const int acol = (lane >> 4) * 4;                      // A: tiles 2,3 at k+4
    const int brow = (lane & 7) + ((lane >> 4) & 1) * 8;   // B: tiles 2,3 rows+8 (next n8)
    const int bcol = ((lane >> 3) & 1) * 4;                // B: tiles 1,3 at k+4

    const float* gA = (MODE == 0) ? p0 : g_vals;
    const float* gB = p1;

    float4 pA[2], pB[2];
    auto loadA = [&](int kt) {
        #pragma unroll
        for (int rep = 0; rep < 2; rep++) {
            int idx = rep * 256 + tid, row = idx >> 2, c4 = idx & 3;
            pA[rep] = *reinterpret_cast<const float4*>(gA + (size_t)(bm + row) * KDIM + kt * BK + c4 * 4);
        }
    };
    auto storeA = [&](int buf) {
        #pragma unroll
        for (int rep = 0; rep < 2; rep++) {
            int idx = rep * 256 + tid, row = idx >> 2, c4 = idx & 3;
            uint32_t* d = &As[buf][row * SAS + c4 * 4];
            d[0] = f2tf32(pA[rep].x); d[1] = f2tf32(pA[rep].y);
            d[2] = f2tf32(pA[rep].z); d[3] = f2tf32(pA[rep].w);
        }
    };
    auto loadB = [&](int kt) {
        #pragma unroll
        for (int rep = 0; rep < 2; rep++) {
            int idx = rep * 256 + tid, row = idx >> 2, c4 = idx & 3;
            pB[rep] = *reinterpret_cast<const float4*>(gB + (size_t)(bn + row) * KDIM + kt * BK + c4 * 4);
        }
    };
    auto storeB = [&](int buf) {
        #pragma unroll
        for (int rep = 0; rep < 2; rep++) {
            int idx = rep * 256 + tid, row = idx >> 2, c4 = idx & 3;
            uint32_t* d = &Bs[buf][row * SAS + c4 * 4];
            d[0] = f2tf32(pB[rep].x); d[1] = f2tf32(pB[rep].y);
            d[2] = f2tf32(pB[rep].z); d[3] = f2tf32(pB[rep].w);
        }
    };

    float acc[4][4][4] = {};
    loadA(0); loadB(0); storeA(0); storeB(0);
    __syncthreads();

    int buf = 0;
    #pragma unroll 1
    for (int kt = 0; kt < KT; kt++) {
        if (kt + 1 < KT) { loadA(kt + 1); loadB(kt + 1); }
        #pragma unroll
        for (int ks = 0; ks < 2; ks++) {
            const int kb = ks * 8;
            uint32_t af[4][4], bfr[4][2];
            #pragma unroll
            for (int i = 0; i < 4; i++) {
                const int rm = warpM * 64 + i * 16;
                ldsm4(af[i][0], af[i][1], af[i][2], af[i][3],
                      &As[buf][(rm + arow) * SAS + kb + acol]);
            }
            #pragma unroll
            for (int j = 0; j < 4; j += 2) {
                const int cn = warpN * 32 + j * 8;
                ldsm4(bfr[j][0], bfr[j][1], bfr[j + 1][0], bfr[j + 1][1],
                      &Bs[buf][(cn + brow) * SAS + kb + bcol]);
            }
            #pragma unroll
            for (int i = 0; i < 4; i++)
                #pragma unroll
                for (int j = 0; j < 4; j++)
                    mma_tf32(acc[i][j], af[i], bfr[j]);
        }
        if (kt + 1 < KT) {
            storeA(buf ^ 1); storeB(buf ^ 1);
            __syncthreads();
            buf ^= 1;
        }
    }

    #pragma unroll
    for (int i = 0; i < 4; i++) {
        const int rm = bm + warpM * 64 + i * 16;
        const int r0 = rm + g, r1 = rm + g + 8;
        #pragma unroll
        for (int j = 0; j < 4; j++) {
            const int n0 = bn + warpN * 32 + j * 8;
            const int nc = n0 + 2 * tg;
            float c0 = acc[i][j][0], c1 = acc[i][j][1];
            float c2 = acc[i][j][2], c3 = acc[i][j][3];
            if (MODE == 0) {
                const float b0 = bias[nc], b1 = bias[nc + 1];
                const int h = n0 / (3 * HD_);
                const int which = (n0 % (3 * HD_)) / HD_;
                const int d = (n0 % HD_) + 2 * tg;
                float* dst = (which == 0) ? g_q : (which == 1) ? g_k : g_v;
                const int bb0 = r0 >> 11, ss0 = r0 & (S_ - 1);
                const int bb1 = r1 >> 11, ss1 = r1 & (S_ - 1);
                // store tf32-rounded so the fused kernel can cp.async raw bits
                float2 v0 = make_float2(__uint_as_float(f2tf32(c0 + b0)), __uint_as_float(f2tf32(c1 + b1)));
                float2 v1 = make_float2(__uint_as_float(f2tf32(c2 + b0)), __uint_as_float(f2tf32(c3 + b1)));
                *reinterpret_cast<float2*>(dst + ((((size_t)bb0 * H_ + h) * S_ + ss0) * HD_ + d)) = v0;
                *reinterpret_cast<float2*>(dst + ((((size_t)bb1 * H_ + h) * S_ + ss1) * HD_ + d)) = v1;
            } else {
                float* outp = pC ? pC : g_out_scratch;
                const float b0 = bias[nc], b1 = bias[nc + 1];
                *reinterpret_cast<float2*>(outp + (size_t)r0 * D_ + nc) = make_float2(c0 + b0, c1 + b1);
                *reinterpret_cast<float2*>(outp + (size_t)r1 * D_ + nc) = make_float2(c2 + b0, c3 + b1);
            }
        }
    }
}

// ============================================================================
// Fused attention: logits + exact softmax + AV, attn matrix written once.
// Block = (128 q-rows, one bh). 256 threads / 8 warps (2x4 grid). LDSM frags.
// ============================================================================
#define QSTR 68
#define XSTR 76
#define PSTR 132
#define FA_SMEM ((128*QSTR + 2*128*XSTR + 128*PSTR) * 4 + 128 * 4)

__global__ __launch_bounds__(256)
void fused_attn(float* __restrict__ attn_ext) {
    extern __shared__ uint32_t sm[];
    uint32_t* Qs = sm;                       // 128*68
    uint32_t* Xs = Qs + 128 * QSTR;          // 2 * 128*76
    uint32_t* Ps = Xs + 2 * 128 * XSTR;      // 128*132
    float* Lrow  = (float*)(Ps + 128 * PSTR);

    const int tid = threadIdx.x;
    const int wid = tid >> 5, lane = tid & 31;
    const int g = lane >> 2, tg = lane & 3;
    const int warpM = wid >> 2, warpN = wid & 3;   // 2x4
    const int wm = warpM * 64;
    const int bm = blockIdx.x * 128;               // q-row block
    const int bh = blockIdx.y;
    const float sc = 1.0f / (float)HD_;

    // LDSM per-thread coordinates
    const int arow = (lane & 7) + ((lane >> 3) & 1) * 8;
    const int acol = (lane >> 4) * 4;
    const int brow = (lane & 7) + ((lane >> 4) & 1) * 8;
    const int bcol = ((lane >> 3) & 1) * 4;

    const float* gQ = g_q + (size_t)bh * S_ * HD_ + (size_t)bm * HD_;
    const float* gK = g_k + (size_t)bh * S_ * HD_;
    const float* gV = g_v + (size_t)bh * S_ * HD_;
    float* attnp = (attn_ext ? attn_ext : g_attn_scratch) + (size_t)bh * S_ * S_;

    auto load_q = [&]() {
        #pragma unroll
        for (int rep = 0; rep < 8; rep++) {
            int idx = rep * 256 + tid, row = idx >> 4, q4 = idx & 15;
            cpa16(&Qs[row * QSTR + q4 * 4], gQ + row * HD_ + q4 * 4);
        }
    };
    auto load_kv = [&](const float* src, int kt, int b) {
        const float* base = src + (size_t)kt * 128 * HD_;
        #pragma unroll
        for (int rep = 0; rep < 8; rep++) {
            int idx = rep * 256 + tid, row = idx >> 4, q4 = idx & 15;
            cpa16(&Xs[b * 128 * XSTR + row * XSTR + q4 * 4], base + row * HD_ + q4 * 4);
        }
    };

    // ---- S = Q @ K^T tile (128x128), K in Xs[b], LDSM fragment loads ----
    auto compute_S = [&](int b, float acc[4][4][4]) {
        #pragma unroll
        for (int i = 0; i < 4; i++)
            #pragma unroll
            for (int j = 0; j < 4; j++)
                #pragma unroll
                for (int e = 0; e < 4; e++) acc[i][j][e] = 0.0f;
        const uint32_t* Kb = Xs + b * 128 * XSTR;
        #pragma unroll
        for (int ks = 0; ks < 8; ks++) {
            const int kb = ks * 8;
            uint32_t af[4][4], bfr[4][2];
            #pragma unroll
            for (int i = 0; i < 4; i++) {
                const int rm = wm + i * 16;
                ldsm4(af[i][0], af[i][1], af[i][2], af[i][3],
                      &Qs[(rm + arow) * QSTR + kb + acol]);
            }
            #pragma unroll
            for (int j = 0; j < 4; j += 2) {
                const int cn = warpN * 32 + j * 8;
                ldsm4(bfr[j][0], bfr[j][1], bfr[j + 1][0], bfr[j + 1][1],
                      &Kb[(cn + brow) * XSTR + kb + bcol]);
            }
            #pragma unroll
            for (int i = 0; i < 4; i++)
                #pragma unroll
                for (int j = 0; j < 4; j++)
                    mma_tf32(acc[i][j], af[i], bfr[j]);
        }
    };

    // ---- prologue ----
    if (tid < 128) Lrow[tid] = 0.0f;
    load_q();
    load_kv(gK, 0, 0);
    CP_COMMIT;
    CP_WAIT0;
    __syncthreads();

    // ================= pass 1: row sums of exp =================
    float lp[4][2] = {};
    int a = 0;
    #pragma unroll 1
    for (int kt = 0; kt < 16; kt++) {
        if (kt < 15) { load_kv(gK, kt + 1, a ^ 1); CP_COMMIT; }
        float acc[4][4][4];
        compute_S(a, acc);
        #pragma unroll
        for (int i = 0; i < 4; i++)
            #pragma unroll
            for (int j = 0; j < 4; j++) {
                lp[i][0] += __expf(acc[i][j][0] * sc) + __expf(acc[i][j][1] * sc);
                lp[i][1] += __expf(acc[i][j][2] * sc) + __expf(acc[i][j][3] * sc);
            }
        if (kt < 15) { CP_WAIT0; __syncthreads(); a ^= 1; }
    }
    #pragma unroll
    for (int i = 0; i < 4; i++)
        #pragma unroll
        for (int h = 0; h < 2; h++) {
            float v = lp[i][h];
            v += __shfl_xor_sync(0xffffffff, v, 1);
            v += __shfl_xor_sync(0xffffffff, v, 2);
            if (tg == 0) atomicAdd(&Lrow[wm + i * 16 + h * 8 + g], v);
        }
    __syncthreads();
    if (tid < 128) Lrow[tid] = 1.0f / Lrow[tid];

    // reload K[0] for pass 2
    load_kv(gK, 0, a ^ 1);
    CP_COMMIT;
    CP_WAIT0;
    a ^= 1;
    __syncthreads();

    // ================= pass 2: attn write + O accumulation =================
    float oacc[4][2][4] = {};
    #pragma unroll 1
    for (int kt = 0; kt < 16; kt++) {
        if (kt < 15) { load_kv(gK, kt + 1, a ^ 1); CP_COMMIT; }
        float acc[4][4][4];
        compute_S(a, acc);
        __syncthreads();                       // all warps done reading K in Xs[a]
        load_kv(gV, kt, a); CP_COMMIT;         // V[kt] overwrites K[kt]

        #pragma unroll
        for (int i = 0; i < 4; i++) {
            const int r0 = wm + i * 16 + g, r1 = r0 + 8;
            const float li0 = Lrow[r0], li1 = Lrow[r1];
            #pragma unroll
            for (int j = 0; j < 4; j++) {
                const int col = warpN * 32 + j * 8 + 2 * tg;
                float p0 = __expf(acc[i][j][0] * sc) * li0;
                float p1 = __expf(acc[i][j][1] * sc) * li0;
                float p2 = __expf(acc[i][j][2] * sc) * li1;
                float p3 = __expf(acc[i][j][3] * sc) * li1;
                *reinterpret_cast<float2*>(attnp + (size_t)(bm + r0) * S_ + kt * 128 + col) = make_float2(p0, p1);
                *reinterpret_cast<float2*>(attnp + (size_t)(bm + r1) * S_ + kt * 128 + col) = make_float2(p2, p3);
                Ps[r0 * PSTR + col]     = f2tf32(p0);
                Ps[r0 * PSTR + col + 1] = f2tf32(p1);
                Ps[r1 * PSTR + col]     = f2tf32(p2);
                Ps[r1 * PSTR + col + 1] = f2tf32(p3);
            }
        }
        CP_WAIT0;
        __syncthreads();   // Ps + V visible

        // O += P @ V  (P A-frags via LDSM; V scalar [k][n])
        const uint32_t* Vb = Xs + a * 128 * XSTR;
        #pragma unroll
        for (int k8 = 0; k8 < 16; k8++) {
            const int kb = k8 * 8;
            uint32_t af[4][4], bfr[2][2];
            #pragma unroll
            for (int i = 0; i < 4; i++) {
                const int rm = wm + i * 16;
                ldsm4(af[i][0], af[i][1], af[i][2], af[i][3],
                      &Ps[(rm + arow) * PSTR + kb + acol]);
            }
            #pragma unroll
            for (int j = 0; j < 2; j++) {
                const int cn = warpN * 16 + j * 8 + g;
                bfr[j][0] = Vb[(kb + tg) * XSTR + cn];
                bfr[j][1] = Vb[(kb + tg + 4) * XSTR + cn];
            }
            #pragma unroll
            for (int i = 0; i < 4; i++)
                #pragma unroll
                for (int j = 0; j < 2; j++)
                    mma_tf32(oacc[i][j], af[i], bfr[j]);
        }
        if (kt < 15) {
            __syncthreads();
            a ^= 1;
        }
    }

    // ---- epilogue: O (128x64) -> g_vals (tf32-rounded; proj re-rounds anyway) ----
    const int bb = bh >> 4, h = bh & 15;
    float* vbase = g_vals + (size_t)bb * S_ * E_ + (size_t)h * HD_;
    #pragma unroll
    for (int i = 0; i < 4; i++) {
        const int r0 = bm + wm + i * 16 + g, r1 = r0 + 8;
        #pragma unroll
        for (int j = 0; j < 2; j++) {
            const int cn = warpN * 16 + j * 8 + 2 * tg;
            *reinterpret_cast<float2*>(vbase + (size_t)r0 * E_ + cn) = make_float2(oacc[i][j][0], oacc[i][j][1]);
            *reinterpret_cast<float2*>(vbase + (size_t)r1 * E_ + cn) = make_float2(oacc[i][j][2], oacc[i][j][3]);
        }
    }
}

// ============================================================================
// Launch. Inputs: x, w_qkv, b_qkv, w_out, b_out.
// ============================================================================
extern "C" void kernel_launch(void* const* d_in, const int* in_sizes, int n_in,
                              void* d_out, int out_size) {
    const float* x     = (const float*)d_in[0];
    const float* w_qkv = (const float*)d_in[1];
    const float* b_qkv = (const float*)d_in[2];
    const float* w_out = (const float*)d_in[3];
    const float* b_out = (const float*)d_in[4];
    float* dout = (float*)d_out;

    const long long OUTN  = (long long)MTOT * D_;
    const long long ATTNN = (long long)BHN * S_ * S_;
    float* out_ext  = nullptr;
    float* attn_ext = nullptr;
    const long long osz = (long long)out_size;
    if (osz >= OUTN + ATTNN) { out_ext = dout; attn_ext = dout + OUTN; }
    else if (osz == ATTNN)   { attn_ext = dout; }
    else                     { out_ext = dout; }

    cudaFuncSetAttribute(fused_attn, cudaFuncAttributeMaxDynamicSharedMemorySize, FA_SMEM);

    dim3 t(256);
    mma_gemm<0><<<dim3(NQKV / 128, MTOT / 128), t>>>(x, w_qkv, b_qkv, nullptr);
    fused_attn<<<dim3(S_ / 128, BHN), t, FA_SMEM>>>(attn_ext);
    mma_gemm<3><<<dim3(D_ / 128, MTOT / 128), t>>>(nullptr, w_out, b_out, out_ext);
}

// round 5
// speedup vs baseline: 1.4968x; 1.4968x over previous
#include <cuda_runtime.h>
#include <cuda_bf16.h>
#include <cstdint>

// Problem dims (fixed by reference)
#define B_   2
#define S_   2048
#define D_   1024
#define E_   1024
#define H_   16
#define HD_  64
#define MTOT (B_*S_)        // 4096
#define NQKV (3*E_)         // 3072
#define BHN  (B_*H_)        // 32

// ---- static device scratch (no allocations allowed) ----
__device__ __align__(256) float g_q[(size_t)BHN * S_ * HD_];       // tf32-rounded
__device__ __align__(256) float g_k[(size_t)BHN * S_ * HD_];
__device__ __align__(256) float g_v[(size_t)BHN * S_ * HD_];
__device__ __align__(256) float g_vals[(size_t)MTOT * E_];         // tf32-rounded O
__device__ __align__(256) float g_x_r[(size_t)MTOT * D_];          // tf32-rounded x
__device__ __align__(256) float g_wqkv_r[(size_t)NQKV * D_];       // tf32-rounded w_qkv
__device__ __align__(256) float g_wout_r[(size_t)D_ * E_];         // tf32-rounded w_out
__device__ __align__(256) float g_out_scratch[(size_t)MTOT * D_];
__device__ __align__(256) float g_attn_scratch[(size_t)BHN * S_ * S_];

__device__ __forceinline__ uint32_t f2tf32(float x) {
    uint32_t u;
    asm("cvt.rna.tf32.f32 %0, %1;" : "=r"(u) : "f"(x));
    return u;
}

__device__ __forceinline__ void mma_tf32(float c[4], const uint32_t a[4], const uint32_t b[2]) {
    asm volatile(
        "mma.sync.aligned.m16n8k8.row.col.f32.tf32.tf32.f32 "
        "{%0,%1,%2,%3}, {%4,%5,%6,%7}, {%8,%9}, {%0,%1,%2,%3};\n"
        : "+f"(c[0]), "+f"(c[1]), "+f"(c[2]), "+f"(c[3])
        : "r"(a[0]), "r"(a[1]), "r"(a[2]), "r"(a[3]), "r"(b[0]), "r"(b[1]));
}

__device__ __forceinline__ void cpa16(void* s, const void* g) {
    uint32_t sa = (uint32_t)__cvta_generic_to_shared(s);
    asm volatile("cp.async.cg.shared.global [%0], [%1], 16;" :: "r"(sa), "l"(g));
}
#define CP_COMMIT asm volatile("cp.async.commit_group;")
#define CP_WAIT0  asm volatile("cp.async.wait_group 0;")
#define CP_WAIT2  asm volatile("cp.async.wait_group 2;")

__device__ __forceinline__ void stg_cs_v2(float* p, float a, float b) {
    asm volatile("st.global.cs.v2.f32 [%0], {%1,%2};" :: "l"(p), "f"(a), "f"(b));
}

// ============================================================================
// Pre-round fp32 arrays to tf32 (cvt.rna) in gmem, so GEMMs can cp.async raw.
// ============================================================================
__global__ void round_kernel(const float* __restrict__ in, float* __restrict__ out, int n) {
    int i = (blockIdx.x * blockDim.x + threadIdx.x) * 4;
    if (i < n) {
        float4 v = *reinterpret_cast<const float4*>(in + i);
        v.x = __uint_as_float(f2tf32(v.x));
        v.y = __uint_as_float(f2tf32(v.y));
        v.z = __uint_as_float(f2tf32(v.z));
        v.w = __uint_as_float(f2tf32(v.w));
        *reinterpret_cast<float4*>(out + i) = v;
    }
}

// ============================================================================
// Dense GEMMs, tf32 tensor cores. Operands pre-rounded -> raw cp.async,
// 4-stage pipeline, scalar-LDS fragments (20-word stride, conflict-free).
// MODE 0: qkv — A=g_x_r[4096,1024], B=g_wqkv_r[3072,1024]; +bias, scatter q/k/v
// MODE 3: proj — A=g_vals[4096,1024], B=g_wout_r[1024,1024]; +bias -> out
// ============================================================================
#define GSTAGES 4
#define GSAS 20
#define GEMM_SMEM (GSTAGES * 2 * 128 * GSAS * 4)   // 81920 B

template<int MODE>
__global__ __launch_bounds__(256)
void mma_gemm(const float* __restrict__ bias, float* __restrict__ pC) {
    constexpr int BM = 128, BN = 128, BK = 16;
    constexpr int KDIM = 1024;
    constexpr int KT = KDIM / BK;

    extern __shared__ uint32_t smg[];
    // stage s: A at smg[s*2*128*GSAS], B at +128*GSAS

    const int tid = threadIdx.x;
    const int wid = tid >> 5, lane = tid & 31;
    const int g = lane >> 2, tg = lane & 3;
    const int warpM = wid / 4, warpN = wid % 4;   // 2x4 warp grid, warp tile 64x32
    const int bm = blockIdx.y * BM;
    const int bn = blockIdx.x * BN;

    const float* gA = (MODE == 0) ? g_x_r : g_vals;
    const float* gB = (MODE == 0) ? g_wqkv_r : g_wout_r;

    const int lrow = tid >> 2, lc4 = (tid & 3) * 4;  // loader coords (64 rows per rep)

    auto issue_stage = [&](int kt, int s) {
        uint32_t* As = smg + (size_t)s * 2 * 128 * GSAS;
        uint32_t* Bs = As + 128 * GSAS;
        #pragma unroll
        for (int rep = 0; rep < 2; rep++) {
            int row = rep * 64 + lrow;
            cpa16(&As[row * GSAS + lc4], gA + (size_t)(bm + row) * KDIM + kt * BK + lc4);
            cpa16(&Bs[row * GSAS + lc4], gB + (size_t)(bn + row) * KDIM + kt * BK + lc4);
        }
        CP_COMMIT;
    };

    #pragma unroll
    for (int s = 0; s < GSTAGES - 1; s++) issue_stage(s, s);

    float acc[4][4][4] = {};

    #pragma unroll 1
    for (int kt = 0; kt < KT; kt++) {
        CP_WAIT2;            // stage kt landed (GSTAGES-2 groups may remain)
        __syncthreads();     // also fences reuse of the stage we're about to overwrite

        const uint32_t* As = smg + (size_t)(kt % GSTAGES) * 2 * 128 * GSAS;
        const uint32_t* Bs = As + 128 * GSAS;

        #pragma unroll
        for (int ks = 0; ks < 2; ks++) {
            const int kb = ks * 8;
            uint32_t af[4][4], bfr[4][2];
            #pragma unroll
            for (int i = 0; i < 4; i++) {
                const int rm = warpM * 64 + i * 16;
                af[i][0] = As[(rm + g) * GSAS + kb + tg];
                af[i][1] = As[(rm + g + 8) * GSAS + kb + tg];
                af[i][2] = As[(rm + g) * GSAS + kb + tg + 4];
                af[i][3] = As[(rm + g + 8) * GSAS + kb + tg + 4];
            }
            #pragma unroll
            for (int j = 0; j < 4; j++) {
                const int cn = warpN * 32 + j * 8;
                bfr[j][0] = Bs[(cn + g) * GSAS + kb + tg];
                bfr[j][1] = Bs[(cn + g) * GSAS + kb + tg + 4];
            }
            #pragma unroll
            for (int i = 0; i < 4; i++)
                #pragma unroll
                for (int j = 0; j < 4; j++)
                    mma_tf32(acc[i][j], af[i], bfr[j]);
        }

        if (kt + GSTAGES - 1 < KT) issue_stage(kt + GSTAGES - 1, (kt + GSTAGES - 1) % GSTAGES);
    }

    #pragma unroll
    for (int i = 0; i < 4; i++) {
        const int rm = bm + warpM * 64 + i * 16;
        const int r0 = rm + g, r1 = rm + g + 8;
        #pragma unroll
        for (int j = 0; j < 4; j++) {
            const int n0 = bn + warpN * 32 + j * 8;
            const int nc = n0 + 2 * tg;
            float c0 = acc[i][j][0], c1 = acc[i][j][1];
            float c2 = acc[i][j][2], c3 = acc[i][j][3];
            if (MODE == 0) {
                const float b0 = bias[nc], b1 = bias[nc + 1];
                const int h = n0 / (3 * HD_);
                const int which = (n0 % (3 * HD_)) / HD_;
                const int d = (n0 % HD_) + 2 * tg;
                float* dst = (which == 0) ? g_q : (which == 1) ? g_k : g_v;
                const int bb0 = r0 >> 11, ss0 = r0 & (S_ - 1);
                const int bb1 = r1 >> 11, ss1 = r1 & (S_ - 1);
                // store tf32-rounded so fused kernel cp.asyncs raw bits
                float2 v0 = make_float2(__uint_as_float(f2tf32(c0 + b0)), __uint_as_float(f2tf32(c1 + b1)));
                float2 v1 = make_float2(__uint_as_float(f2tf32(c2 + b0)), __uint_as_float(f2tf32(c3 + b1)));
                *reinterpret_cast<float2*>(dst + ((((size_t)bb0 * H_ + h) * S_ + ss0) * HD_ + d)) = v0;
                *reinterpret_cast<float2*>(dst + ((((size_t)bb1 * H_ + h) * S_ + ss1) * HD_ + d)) = v1;
            } else {
                float* outp = pC ? pC : g_out_scratch;
                const float b0 = bias[nc], b1 = bias[nc + 1];
                *reinterpret_cast<float2*>(outp + (size_t)r0 * D_ + nc) = make_float2(c0 + b0, c1 + b1);
                *reinterpret_cast<float2*>(outp + (size_t)r1 * D_ + nc) = make_float2(c2 + b0, c3 + b1);
            }
        }
    }
}

// ============================================================================
// Fused attention: logits + exact softmax + AV; attn written once (st.cs).
// Block = (128 q-rows, one bh). 256 threads / 8 warps (2x4). Scalar-LDS frags.
// ============================================================================
#define QSTR 68
#define XSTR 76
#define PSTR 132
#define FA_SMEM ((128*QSTR + 2*128*XSTR + 128*PSTR) * 4 + 128 * 4)

__global__ __launch_bounds__(256)
void fused_attn(float* __restrict__ attn_ext) {
    extern __shared__ uint32_t sm[];
    uint32_t* Qs = sm;                       // 128*68
    uint32_t* Xs = Qs + 128 * QSTR;          // 2 * 128*76
    uint32_t* Ps = Xs + 2 * 128 * XSTR;      // 128*132
    float* Lrow  = (float*)(Ps + 128 * PSTR);

    const int tid = threadIdx.x;
    const int wid = tid >> 5, lane = tid & 31;
    const int g = lane >> 2, tg = lane & 3;
    const int warpM = wid >> 2, warpN = wid & 3;   // 2x4
    const int wm = warpM * 64;
    const int bm = blockIdx.x * 128;
    const int bh = blockIdx.y;
    const float sc = 1.0f / (float)HD_;

    const float* gQ = g_q + (size_t)bh * S_ * HD_ + (size_t)bm * HD_;
    const float* gK = g_k + (size_t)bh * S_ * HD_;
    const float* gV = g_v + (size_t)bh * S_ * HD_;
    float* attnp = (attn_ext ? attn_ext : g_attn_scratch) + (size_t)bh * S_ * S_;

    auto load_q = [&]() {
        #pragma unroll
        for (int rep = 0; rep < 8; rep++) {
            int idx = rep * 256 + tid, row = idx >> 4, q4 = idx & 15;
            cpa16(&Qs[row * QSTR + q4 * 4], gQ + row * HD_ + q4 * 4);
        }
    };
    auto load_kv = [&](const float* src, int kt, int b) {
        const float* base = src + (size_t)kt * 128 * HD_;
        #pragma unroll
        for (int rep = 0; rep < 8; rep++) {
            int idx = rep * 256 + tid, row = idx >> 4, q4 = idx & 15;
            cpa16(&Xs[b * 128 * XSTR + row * XSTR + q4 * 4], base + row * HD_ + q4 * 4);
        }
    };

    auto compute_S = [&](int b, float acc[4][4][4]) {
        #pragma unroll
        for (int i = 0; i < 4; i++)
            #pragma unroll
            for (int j = 0; j < 4; j++)
                #pragma unroll
                for (int e = 0; e < 4; e++) acc[i][j][e] = 0.0f;
        const uint32_t* Kb = Xs + b * 128 * XSTR;
        #pragma unroll
        for (int ks = 0; ks < 8; ks++) {
            const int kb = ks * 8;
            uint32_t af[4][4], bfr[4][2];
            #pragma unroll
            for (int i = 0; i < 4; i++) {
                const int r = wm + i * 16 + g;
                af[i][0] = Qs[r * QSTR + kb + tg];
                af[i][1] = Qs[(r + 8) * QSTR + kb + tg];
                af[i][2] = Qs[r * QSTR + kb + tg + 4];
                af[i][3] = Qs[(r + 8) * QSTR + kb + tg + 4];
            }
            #pragma unroll
            for (int j = 0; j < 4; j++) {
                const int c = warpN * 32 + j * 8 + g;
                bfr[j][0] = Kb[c * XSTR + kb + tg];
                bfr[j][1] = Kb[c * XSTR + kb + tg + 4];
            }
            #pragma unroll
            for (int i = 0; i < 4; i++)
                #pragma unroll
                for (int j = 0; j < 4; j++)
                    mma_tf32(acc[i][j], af[i], bfr[j]);
        }
    };

    // ---- prologue ----
    if (tid < 128) Lrow[tid] = 0.0f;
    load_q();
    load_kv(gK, 0, 0);
    CP_COMMIT;
    CP_WAIT0;
    __syncthreads();

    // ================= pass 1: row sums of exp =================
    float lp[4][2] = {};
    int a = 0;
    #pragma unroll 1
    for (int kt = 0; kt < 16; kt++) {
        if (kt < 15) { load_kv(gK, kt + 1, a ^ 1); CP_COMMIT; }
        float acc[4][4][4];
        compute_S(a, acc);
        #pragma unroll
        for (int i = 0; i < 4; i++)
            #pragma unroll
            for (int j = 0; j < 4; j++) {
                lp[i][0] += __expf(acc[i][j][0] * sc) + __expf(acc[i][j][1] * sc);
                lp[i][1] += __expf(acc[i][j][2] * sc) + __expf(acc[i][j][3] * sc);
            }
        if (kt < 15) { CP_WAIT0; __syncthreads(); a ^= 1; }
    }
    #pragma unroll
    for (int i = 0; i < 4; i++)
        #pragma unroll
        for (int h = 0; h < 2; h++) {
            float v = lp[i][h];
            v += __shfl_xor_sync(0xffffffff, v, 1);
            v += __shfl_xor_sync(0xffffffff, v, 2);
            if (tg == 0) atomicAdd(&Lrow[wm + i * 16 + h * 8 + g], v);
        }
    __syncthreads();
    if (tid < 128) Lrow[tid] = 1.0f / Lrow[tid];

    // reload K[0] for pass 2
    load_kv(gK, 0, a ^ 1);
    CP_COMMIT;
    CP_WAIT0;
    a ^= 1;
    __syncthreads();

    // ================= pass 2: attn write + O accumulation =================
    float oacc[4][2][4] = {};
    #pragma unroll 1
    for (int kt = 0; kt < 16; kt++) {
        if (kt < 15) { load_kv(gK, kt + 1, a ^ 1); CP_COMMIT; }
        float acc[4][4][4];
        compute_S(a, acc);
        __syncthreads();                       // all warps done reading K in Xs[a]
        load_kv(gV, kt, a); CP_COMMIT;         // V[kt] overwrites K[kt]

        #pragma unroll
        for (int i = 0; i < 4; i++) {
            const int r0 = wm + i * 16 + g, r1 = r0 + 8;
            const float li0 = Lrow[r0], li1 = Lrow[r1];
            #pragma unroll
            for (int j = 0; j < 4; j++) {
                const int col = warpN * 32 + j * 8 + 2 * tg;
                float p0 = __expf(acc[i][j][0] * sc) * li0;
                float p1 = __expf(acc[i][j][1] * sc) * li0;
                float p2 = __expf(acc[i][j][2] * sc) * li1;
                float p3 = __expf(acc[i][j][3] * sc) * li1;
                stg_cs_v2(attnp + (size_t)(bm + r0) * S_ + kt * 128 + col, p0, p1);
                stg_cs_v2(attnp + (size_t)(bm + r1) * S_ + kt * 128 + col, p2, p3);
                Ps[r0 * PSTR + col]     = f2tf32(p0);
                Ps[r0 * PSTR + col + 1] = f2tf32(p1);
                Ps[r1 * PSTR + col]     = f2tf32(p2);
                Ps[r1 * PSTR + col + 1] = f2tf32(p3);
            }
        }
        CP_WAIT0;
        __syncthreads();   // Ps + V visible

        const uint32_t* Vb = Xs + a * 128 * XSTR;
        #pragma unroll
        for (int k8 = 0; k8 < 16; k8++) {
            const int kb = k8 * 8;
            uint32_t af[4][4], bfr[2][2];
            #pragma unroll
            for (int i = 0; i < 4; i++) {
                const int r = wm + i * 16 + g;
                af[i][0] = Ps[r * PSTR + kb + tg];
                af[i][1] = Ps[(r + 8) * PSTR + kb + tg];
                af[i][2] = Ps[r * PSTR + kb + tg + 4];
                af[i][3] = Ps[(r + 8) * PSTR + kb + tg + 4];
            }
            #pragma unroll
            for (int j = 0; j < 2; j++) {
                const int cn = warpN * 16 + j * 8 + g;
                bfr[j][0] = Vb[(kb + tg) * XSTR + cn];
                bfr[j][1] = Vb[(kb + tg + 4) * XSTR + cn];
            }
            #pragma unroll
            for (int i = 0; i < 4; i++)
                #pragma unroll
                for (int j = 0; j < 2; j++)
                    mma_tf32(oacc[i][j], af[i], bfr[j]);
        }
        if (kt < 15) {
            __syncthreads();
            a ^= 1;
        }
    }

    // ---- epilogue: O -> g_vals, tf32-rounded so proj can cp.async raw ----
    const int bb = bh >> 4, h = bh & 15;
    float* vbase = g_vals + (size_t)bb * S_ * E_ + (size_t)h * HD_;
    #pragma unroll
    for (int i = 0; i < 4; i++) {
        const int r0 = bm + wm + i * 16 + g, r1 = r0 + 8;
        #pragma unroll
        for (int j = 0; j < 2; j++) {
            const int cn = warpN * 16 + j * 8 + 2 * tg;
            *reinterpret_cast<float2*>(vbase + (size_t)r0 * E_ + cn) =
                make_float2(__uint_as_float(f2tf32(oacc[i][j][0])), __uint_as_float(f2tf32(oacc[i][j][1])));
            *reinterpret_cast<float2*>(vbase + (size_t)r1 * E_ + cn) =
                make_float2(__uint_as_float(f2tf32(oacc[i][j][2])), __uint_as_float(f2tf32(oacc[i][j][3])));
        }
    }
}

// ============================================================================
// Launch. Inputs: x, w_qkv, b_qkv, w_out, b_out.
// ============================================================================
extern "C" void kernel_launch(void* const* d_in, const int* in_sizes, int n_in,
                              void* d_out, int out_size) {
    const float* x     = (const float*)d_in[0];
    const float* w_qkv = (const float*)d_in[1];
    const float* b_qkv = (const float*)d_in[2];
    const float* w_out = (const float*)d_in[3];
    const float* b_out = (const float*)d_in[4];
    float* dout = (float*)d_out;

    const long long OUTN  = (long long)MTOT * D_;
    const long long ATTNN = (long long)BHN * S_ * S_;
    float* out_ext  = nullptr;
    float* attn_ext = nullptr;
    const long long osz = (long long)out_size;
    if (osz >= OUTN + ATTNN) { out_ext = dout; attn_ext = dout + OUTN; }
    else if (osz == ATTNN)   { attn_ext = dout; }
    else                     { out_ext = dout; }

    cudaFuncSetAttribute(fused_attn, cudaFuncAttributeMaxDynamicSharedMemorySize, FA_SMEM);
    cudaFuncSetAttribute(mma_gemm<0>, cudaFuncAttributeMaxDynamicSharedMemorySize, GEMM_SMEM);
    cudaFuncSetAttribute(mma_gemm<3>, cudaFuncAttributeMaxDynamicSharedMemorySize, GEMM_SMEM);

    float* xr; float* wqr; float* wor;
    cudaGetSymbolAddress((void**)&xr,  g_x_r);
    cudaGetSymbolAddress((void**)&wqr, g_wqkv_r);
    cudaGetSymbolAddress((void**)&wor, g_wout_r);

    dim3 t(256);
    round_kernel<<<(MTOT * D_ / 4 + 255) / 256, 256>>>(x, xr, MTOT * D_);
    round_kernel<<<(NQKV * D_ / 4 + 255) / 256, 256>>>(w_qkv, wqr, NQKV * D_);
    round_kernel<<<(D_ * E_ / 4 + 255) / 256, 256>>>(w_out, wor, D_ * E_);

    mma_gemm<0><<<dim3(NQKV / 128, MTOT / 128), t, GEMM_SMEM>>>(b_qkv, nullptr);
    fused_attn<<<dim3(S_ / 128, BHN), t, FA_SMEM>>>(attn_ext);
    mma_gemm<3><<<dim3(D_ / 128, MTOT / 128), t, GEMM_SMEM>>>(b_out, out_ext);
}